// round 2
// baseline (speedup 1.0000x reference)
#include <cuda_runtime.h>

// ----------------------------------------------------------------------------
// SimpleVQVAE forward: enc conv3(80->512) relu conv3(512->512) -> VQ(K=1024,D=512)
//                      -> dec conv3(512->512) relu conv3(512->80)
// Activations kept in [B, T, C] layout (channel-contiguous).
// ----------------------------------------------------------------------------

#define TILE 64
#define KC   16

static __device__ float g_bufA[16UL * 2048 * 512];     // 64 MB
static __device__ float g_bufB[16UL * 2048 * 512];     // 64 MB
static __device__ float g_scores[32768UL * 1024];      // 128 MB
static __device__ float g_wT[3UL * 512 * 1024];        // transposed weights / codebook^T
static __device__ float g_cnorm[1024];
static __device__ int   g_idx[32768];

// ---- weight transpose: w[CO][CI][TAPS] -> wT[TAPS][CI][CO_pad], zero pad ----
__global__ void transpose_w(const float* __restrict__ w, float* __restrict__ wT,
                            int CO, int CI, int TAPS, int CO_pad) {
    long total = (long)TAPS * CI * CO_pad;
    for (long i = (long)blockIdx.x * blockDim.x + threadIdx.x; i < total;
         i += (long)gridDim.x * blockDim.x) {
        int  co = (int)(i % CO_pad);
        long r  = i / CO_pad;
        int  ci = (int)(r % CI);
        int  k  = (int)(r / CI);
        wT[i] = (co < CO) ? w[((long)co * CI + ci) * TAPS + k] : 0.f;
    }
}

// ---- fused conv1d-as-GEMM (implicit im2col), also plain GEMM when TAPS==1 ---
// y[b,t,co] = relu?( alpha * sum_{k,ci} wT[k][ci][co] * x[b, t+k-1, ci] + bias )
template <int TAPS, bool RELU, bool BIAS>
__global__ void __launch_bounds__(256)
conv_gemm(const float* __restrict__ x, const float* __restrict__ wT,
          const float* __restrict__ addvec, float* __restrict__ y,
          int T, int CI, int CO, int CO_pad, float alpha) {
    __shared__ float As[KC][TILE + 4];
    __shared__ float Bs[KC][TILE];

    const int t0  = blockIdx.x * TILE;
    const int co0 = blockIdx.y * TILE;
    const float* xb = x + (size_t)blockIdx.z * T * CI;
    float*       yb = y + (size_t)blockIdx.z * T * CO;

    const int tid = threadIdx.x;
    const int tx = tid & 15, ty = tid >> 4;     // compute 4x4 micro-tile coords
    const int lt = tid >> 2, lc = tid & 3;      // A-load: 64 rows x 4 float4
    const int br = tid >> 4, bc = tid & 15;     // B-load: 16 rows x 16 float4

    float acc[4][4];
#pragma unroll
    for (int i = 0; i < 4; i++)
#pragma unroll
        for (int j = 0; j < 4; j++) acc[i][j] = 0.f;

#pragma unroll
    for (int k = 0; k < TAPS; k++) {
        const int tshift = (TAPS == 1) ? 0 : (k - 1);
        for (int ci0 = 0; ci0 < CI; ci0 += KC) {
            // ---- load A tile (coalesced along channels, transposed to smem) ----
            int tg = t0 + lt + tshift;
            float4 av = make_float4(0.f, 0.f, 0.f, 0.f);
            if (tg >= 0 && tg < T)
                av = *reinterpret_cast<const float4*>(xb + (size_t)tg * CI + ci0 + lc * 4);
            As[lc * 4 + 0][lt] = av.x;
            As[lc * 4 + 1][lt] = av.y;
            As[lc * 4 + 2][lt] = av.z;
            As[lc * 4 + 3][lt] = av.w;
            // ---- load B tile (coalesced, pre-transposed weights) ----
            const float* wrow = wT + ((size_t)k * CI + ci0 + br) * CO_pad + co0;
            *reinterpret_cast<float4*>(&Bs[br][bc * 4]) =
                *reinterpret_cast<const float4*>(wrow + bc * 4);
            __syncthreads();

#pragma unroll
            for (int kk = 0; kk < KC; kk++) {
                float4 a  = *reinterpret_cast<const float4*>(&As[kk][ty * 4]);
                float4 bv = *reinterpret_cast<const float4*>(&Bs[kk][tx * 4]);
                acc[0][0] += a.x * bv.x; acc[0][1] += a.x * bv.y;
                acc[0][2] += a.x * bv.z; acc[0][3] += a.x * bv.w;
                acc[1][0] += a.y * bv.x; acc[1][1] += a.y * bv.y;
                acc[1][2] += a.y * bv.z; acc[1][3] += a.y * bv.w;
                acc[2][0] += a.z * bv.x; acc[2][1] += a.z * bv.y;
                acc[2][2] += a.z * bv.z; acc[2][3] += a.z * bv.w;
                acc[3][0] += a.w * bv.x; acc[3][1] += a.w * bv.y;
                acc[3][2] += a.w * bv.z; acc[3][3] += a.w * bv.w;
            }
            __syncthreads();
        }
    }

#pragma unroll
    for (int i = 0; i < 4; i++) {
        int tg = t0 + ty * 4 + i;
#pragma unroll
        for (int j = 0; j < 4; j++) {
            int cog = co0 + tx * 4 + j;
            if (cog < CO) {
                float v = alpha * acc[i][j];
                if (BIAS) v += addvec[cog];
                if (RELU) v = fmaxf(v, 0.f);
                yb[(size_t)tg * CO + cog] = v;
            }
        }
    }
}

// ---- per-codeword squared norm: cn[k] = sum_d cb[k][d]^2 (warp per row) ----
__global__ void cnorm_kernel(const float* __restrict__ cb, float* __restrict__ cn) {
    int row  = blockIdx.x * (blockDim.x >> 5) + (threadIdx.x >> 5);
    int lane = threadIdx.x & 31;
    if (row >= 1024) return;
    const float* c = cb + (size_t)row * 512;
    float s = 0.f;
    for (int i = lane; i < 512; i += 32) { float v = c[i]; s += v * v; }
#pragma unroll
    for (int o = 16; o; o >>= 1) s += __shfl_xor_sync(0xffffffffu, s, o);
    if (lane == 0) cn[row] = s;
}

// ---- argmin over 1024 (score + cnorm) per row (warp/row, first-index ties) ----
__global__ void argmin_kernel(const float* __restrict__ s, const float* __restrict__ cn,
                              int* __restrict__ idx) {
    int row  = blockIdx.x * (blockDim.x >> 5) + (threadIdx.x >> 5);
    int lane = threadIdx.x & 31;
    if (row >= 32768) return;
    const float* r = s + (size_t)row * 1024;
    float best = 3.402823466e38f;
    int   bi   = 0x7fffffff;
#pragma unroll 4
    for (int i = 0; i < 32; i++) {
        int   c = lane + (i << 5);
        float v = r[c] + cn[c];
        if (v < best || (v == best && c < bi)) { best = v; bi = c; }
    }
#pragma unroll
    for (int o = 16; o; o >>= 1) {
        float ov = __shfl_xor_sync(0xffffffffu, best, o);
        int   oi = __shfl_xor_sync(0xffffffffu, bi, o);
        if (ov < best || (ov == best && oi < bi)) { best = ov; bi = oi; }
    }
    if (lane == 0) idx[row] = bi;
}

// ---- gather codebook rows: q[n][:] = cb[idx[n]][:] -------------------------
__global__ void gather_kernel(const float* __restrict__ cb, const int* __restrict__ idx,
                              float* __restrict__ q) {
    long gid = (long)blockIdx.x * blockDim.x + threadIdx.x;   // one float4 each
    if (gid >= 32768L * 128) return;
    int n  = (int)(gid >> 7);
    int d4 = (int)(gid & 127);
    reinterpret_cast<float4*>(q)[(long)n * 128 + d4] =
        reinterpret_cast<const float4*>(cb)[(long)idx[n] * 128 + d4];
}

__global__ void idx_to_float(const int* __restrict__ idx, float* __restrict__ out, int n) {
    int i = blockIdx.x * blockDim.x + threadIdx.x;
    if (i < n) out[i] = (float)idx[i];
}

// ----------------------------------------------------------------------------
extern "C" void kernel_launch(void* const* d_in, const int* in_sizes, int n_in,
                              void* d_out, int out_size) {
    const float* mels   = (const float*)d_in[0];
    const float* enc_w1 = (const float*)d_in[1];
    const float* enc_b1 = (const float*)d_in[2];
    const float* enc_w2 = (const float*)d_in[3];
    const float* enc_b2 = (const float*)d_in[4];
    const float* cb     = (const float*)d_in[5];
    const float* dec_w1 = (const float*)d_in[6];
    const float* dec_b1 = (const float*)d_in[7];
    const float* dec_w2 = (const float*)d_in[8];
    const float* dec_b2 = (const float*)d_in[9];

    float *bufA, *bufB, *scores, *wT, *cn;
    int*   idxp;
    cudaGetSymbolAddress((void**)&bufA,   g_bufA);
    cudaGetSymbolAddress((void**)&bufB,   g_bufB);
    cudaGetSymbolAddress((void**)&scores, g_scores);
    cudaGetSymbolAddress((void**)&wT,     g_wT);
    cudaGetSymbolAddress((void**)&cn,     g_cnorm);
    cudaGetSymbolAddress((void**)&idxp,   g_idx);

    const int B = 16, T = 2048, IN = 80, H = 512, D = 512, K = 1024;
    const int BT = B * T;                 // 32768
    const int RECON = B * T * IN;         // 2621440

    // ---- encoder conv1: mels[B,T,80] -> bufA[B,T,512], relu ----
    transpose_w<<<256, 256>>>(enc_w1, wT, H, IN, 3, H);
    conv_gemm<3, true, true><<<dim3(T / TILE, H / TILE, B), 256>>>(
        mels, wT, enc_b1, bufA, T, IN, H, H, 1.f);

    // ---- encoder conv2: bufA -> bufB (z) ----
    transpose_w<<<256, 256>>>(enc_w2, wT, D, H, 3, D);
    conv_gemm<3, false, true><<<dim3(T / TILE, D / TILE, B), 256>>>(
        bufA, wT, enc_b2, bufB, T, H, D, D, 1.f);

    // ---- VQ: scores[n,k] = -2 z_n . c_k ; argmin adds ||c_k||^2 on the fly ----
    cnorm_kernel<<<1024 / 8, 256>>>(cb, cn);
    transpose_w<<<256, 256>>>(cb, wT, K, D, 1, K);            // cb^T: [D][K]
    conv_gemm<1, false, false><<<dim3(BT / TILE, K / TILE, 1), 256>>>(
        bufB, wT, nullptr, scores, BT, D, K, K, -2.f);
    argmin_kernel<<<BT / 8, 256>>>(scores, cn, idxp);
    gather_kernel<<<(BT * 128 + 255) / 256, 256>>>(cb, idxp, bufA);  // q -> bufA

    // ---- decoder conv1: bufA -> bufB, relu ----
    transpose_w<<<256, 256>>>(dec_w1, wT, H, D, 3, H);
    conv_gemm<3, true, true><<<dim3(T / TILE, H / TILE, B), 256>>>(
        bufA, wT, dec_b1, bufB, T, D, H, H, 1.f);

    // ---- decoder conv2: bufB -> recon (directly into d_out, [B,T,80]) ----
    transpose_w<<<256, 256>>>(dec_w2, wT, IN, H, 3, 128);
    float* recon = (float*)d_out;
    conv_gemm<3, false, true><<<dim3(T / TILE, 2, B), 256>>>(
        bufB, wT, dec_b2, recon, T, H, IN, 128, 1.f);

    // ---- idx tail (tuple output flattened as float32), if the harness expects it ----
    if (out_size >= RECON + BT) {
        idx_to_float<<<(BT + 255) / 256, 256>>>(idxp, recon + RECON, BT);
    }
}

// round 3
// speedup vs baseline: 1.0132x; 1.0132x over previous
#include <cuda_runtime.h>

// ----------------------------------------------------------------------------
// SimpleVQVAE forward: enc conv3(80->512) relu conv3(512->512) -> VQ(K=1024,D=512)
//                      -> dec conv3(512->512) relu conv3(512->80)
// Activations kept in [B, T, C] layout (channel-contiguous).
// GEMM: 128x128 block tile, 8x8 micro-tile, BK=16 (1 B LDS per FFMA).
// ----------------------------------------------------------------------------

#define BM 128
#define BN 128
#define BK 16

static __device__ float g_bufA[16UL * 2048 * 512];     // 64 MB
static __device__ float g_bufB[16UL * 2048 * 512];     // 64 MB
static __device__ float g_scores[32768UL * 1024];      // 128 MB
static __device__ float g_wT[3UL * 512 * 1024];        // transposed weights / codebook^T
static __device__ float g_cnorm[1024];
static __device__ int   g_idx[32768];

// ---- weight transpose: w[CO][CI][TAPS] -> wT[TAPS][CI][CO_pad], zero pad ----
__global__ void transpose_w(const float* __restrict__ w, float* __restrict__ wT,
                            int CO, int CI, int TAPS, int CO_pad) {
    long total = (long)TAPS * CI * CO_pad;
    for (long i = (long)blockIdx.x * blockDim.x + threadIdx.x; i < total;
         i += (long)gridDim.x * blockDim.x) {
        int  co = (int)(i % CO_pad);
        long r  = i / CO_pad;
        int  ci = (int)(r % CI);
        int  k  = (int)(r / CI);
        wT[i] = (co < CO) ? w[((long)co * CI + ci) * TAPS + k] : 0.f;
    }
}

// ---- fused conv1d-as-GEMM (implicit im2col), plain GEMM when TAPS==1 -------
// y[b,t,co] = relu?( alpha * sum_{k,ci} wT[k][ci][co] * x[b, t+k-1, ci] + bias )
template <int TAPS, bool RELU, bool BIAS>
__global__ void __launch_bounds__(256)
conv_gemm(const float* __restrict__ x, const float* __restrict__ wT,
          const float* __restrict__ addvec, float* __restrict__ y,
          int T, int CI, int CO, int CO_pad, float alpha) {
    __shared__ float As[BK][BM + 4];
    __shared__ float Bs[BK][BN];

    const int t0  = blockIdx.x * BM;
    const int co0 = blockIdx.y * BN;
    const float* xb = x + (size_t)blockIdx.z * T * CI;
    float*       yb = y + (size_t)blockIdx.z * T * CO;

    const int tid = threadIdx.x;
    const int tx = tid & 15, ty = tid >> 4;          // 8x8 micro-tile coords
    const int arow = tid & 127, ahalf = tid >> 7;    // A-load: row, ci-half (8 ci each)
    const int br = tid >> 4, bc = tid & 15;          // B-load: 16 k-rows x 16 col-chunks

    float acc[8][8];
#pragma unroll
    for (int i = 0; i < 8; i++)
#pragma unroll
        for (int j = 0; j < 8; j++) acc[i][j] = 0.f;

#pragma unroll
    for (int k = 0; k < TAPS; k++) {
        const int tshift = (TAPS == 1) ? 0 : (k - 1);
        for (int ci0 = 0; ci0 < CI; ci0 += BK) {
            // ---- load A tile: 128 rows x 16 ci, transposed into smem ----
            {
                int tg = t0 + arow + tshift;
                float4 a0 = make_float4(0.f, 0.f, 0.f, 0.f);
                float4 a1 = make_float4(0.f, 0.f, 0.f, 0.f);
                if (tg >= 0 && tg < T) {
                    const float* p = xb + (size_t)tg * CI + ci0 + ahalf * 8;
                    a0 = *reinterpret_cast<const float4*>(p);
                    a1 = *reinterpret_cast<const float4*>(p + 4);
                }
                int c = ahalf * 8;
                As[c + 0][arow] = a0.x; As[c + 1][arow] = a0.y;
                As[c + 2][arow] = a0.z; As[c + 3][arow] = a0.w;
                As[c + 4][arow] = a1.x; As[c + 5][arow] = a1.y;
                As[c + 6][arow] = a1.z; As[c + 7][arow] = a1.w;
            }
            // ---- load B tile: 16 k-rows x 128 cols (coalesced) ----
            {
                const float* wrow = wT + ((size_t)k * CI + ci0 + br) * CO_pad + co0 + bc * 8;
                *reinterpret_cast<float4*>(&Bs[br][bc * 8])     =
                    *reinterpret_cast<const float4*>(wrow);
                *reinterpret_cast<float4*>(&Bs[br][bc * 8 + 4]) =
                    *reinterpret_cast<const float4*>(wrow + 4);
            }
            __syncthreads();

#pragma unroll
            for (int kk = 0; kk < BK; kk++) {
                float a[8], b[8];
                *reinterpret_cast<float4*>(&a[0]) =
                    *reinterpret_cast<const float4*>(&As[kk][ty * 8]);
                *reinterpret_cast<float4*>(&a[4]) =
                    *reinterpret_cast<const float4*>(&As[kk][ty * 8 + 4]);
                *reinterpret_cast<float4*>(&b[0]) =
                    *reinterpret_cast<const float4*>(&Bs[kk][tx * 8]);
                *reinterpret_cast<float4*>(&b[4]) =
                    *reinterpret_cast<const float4*>(&Bs[kk][tx * 8 + 4]);
#pragma unroll
                for (int i = 0; i < 8; i++)
#pragma unroll
                    for (int j = 0; j < 8; j++)
                        acc[i][j] += a[i] * b[j];
            }
            __syncthreads();
        }
    }

#pragma unroll
    for (int i = 0; i < 8; i++) {
        int tg = t0 + ty * 8 + i;
        float* yrow = yb + (size_t)tg * CO;
#pragma unroll
        for (int j = 0; j < 8; j++) {
            int cog = co0 + tx * 8 + j;
            if (cog < CO) {
                float v = alpha * acc[i][j];
                if (BIAS) v += addvec[cog];
                if (RELU) v = fmaxf(v, 0.f);
                yrow[cog] = v;
            }
        }
    }
}

// ---- per-codeword squared norm: cn[k] = sum_d cb[k][d]^2 (warp per row) ----
__global__ void cnorm_kernel(const float* __restrict__ cb, float* __restrict__ cn) {
    int row  = blockIdx.x * (blockDim.x >> 5) + (threadIdx.x >> 5);
    int lane = threadIdx.x & 31;
    if (row >= 1024) return;
    const float* c = cb + (size_t)row * 512;
    float s = 0.f;
    for (int i = lane; i < 512; i += 32) { float v = c[i]; s += v * v; }
#pragma unroll
    for (int o = 16; o; o >>= 1) s += __shfl_xor_sync(0xffffffffu, s, o);
    if (lane == 0) cn[row] = s;
}

// ---- argmin over 1024 (score + cnorm) per row (warp/row, first-index ties) ----
__global__ void argmin_kernel(const float* __restrict__ s, const float* __restrict__ cn,
                              int* __restrict__ idx) {
    int row  = blockIdx.x * (blockDim.x >> 5) + (threadIdx.x >> 5);
    int lane = threadIdx.x & 31;
    if (row >= 32768) return;
    const float* r = s + (size_t)row * 1024;
    float best = 3.402823466e38f;
    int   bi   = 0x7fffffff;
#pragma unroll 4
    for (int i = 0; i < 32; i++) {
        int   c = lane + (i << 5);
        float v = r[c] + cn[c];
        if (v < best || (v == best && c < bi)) { best = v; bi = c; }
    }
#pragma unroll
    for (int o = 16; o; o >>= 1) {
        float ov = __shfl_xor_sync(0xffffffffu, best, o);
        int   oi = __shfl_xor_sync(0xffffffffu, bi, o);
        if (ov < best || (ov == best && oi < bi)) { best = ov; bi = oi; }
    }
    if (lane == 0) idx[row] = bi;
}

// ---- gather codebook rows: q[n][:] = cb[idx[n]][:] -------------------------
__global__ void gather_kernel(const float* __restrict__ cb, const int* __restrict__ idx,
                              float* __restrict__ q) {
    long gid = (long)blockIdx.x * blockDim.x + threadIdx.x;   // one float4 each
    if (gid >= 32768L * 128) return;
    int n  = (int)(gid >> 7);
    int d4 = (int)(gid & 127);
    reinterpret_cast<float4*>(q)[(long)n * 128 + d4] =
        reinterpret_cast<const float4*>(cb)[(long)idx[n] * 128 + d4];
}

__global__ void idx_to_float(const int* __restrict__ idx, float* __restrict__ out, int n) {
    int i = blockIdx.x * blockDim.x + threadIdx.x;
    if (i < n) out[i] = (float)idx[i];
}

// ----------------------------------------------------------------------------
extern "C" void kernel_launch(void* const* d_in, const int* in_sizes, int n_in,
                              void* d_out, int out_size) {
    const float* mels   = (const float*)d_in[0];
    const float* enc_w1 = (const float*)d_in[1];
    const float* enc_b1 = (const float*)d_in[2];
    const float* enc_w2 = (const float*)d_in[3];
    const float* enc_b2 = (const float*)d_in[4];
    const float* cb     = (const float*)d_in[5];
    const float* dec_w1 = (const float*)d_in[6];
    const float* dec_b1 = (const float*)d_in[7];
    const float* dec_w2 = (const float*)d_in[8];
    const float* dec_b2 = (const float*)d_in[9];

    float *bufA, *bufB, *scores, *wT, *cn;
    int*   idxp;
    cudaGetSymbolAddress((void**)&bufA,   g_bufA);
    cudaGetSymbolAddress((void**)&bufB,   g_bufB);
    cudaGetSymbolAddress((void**)&scores, g_scores);
    cudaGetSymbolAddress((void**)&wT,     g_wT);
    cudaGetSymbolAddress((void**)&cn,     g_cnorm);
    cudaGetSymbolAddress((void**)&idxp,   g_idx);

    const int B = 16, T = 2048, IN = 80, H = 512, D = 512, K = 1024;
    const int BT = B * T;                 // 32768
    const int RECON = B * T * IN;         // 2621440

    // ---- encoder conv1: mels[B,T,80] -> bufA[B,T,512], relu ----
    transpose_w<<<256, 256>>>(enc_w1, wT, H, IN, 3, H);
    conv_gemm<3, true, true><<<dim3(T / BM, H / BN, B), 256>>>(
        mels, wT, enc_b1, bufA, T, IN, H, H, 1.f);

    // ---- encoder conv2: bufA -> bufB (z) ----
    transpose_w<<<256, 256>>>(enc_w2, wT, D, H, 3, D);
    conv_gemm<3, false, true><<<dim3(T / BM, D / BN, B), 256>>>(
        bufA, wT, enc_b2, bufB, T, H, D, D, 1.f);

    // ---- VQ: scores[n,k] = -2 z_n . c_k ; argmin adds ||c_k||^2 on the fly ----
    cnorm_kernel<<<1024 / 8, 256>>>(cb, cn);
    transpose_w<<<256, 256>>>(cb, wT, K, D, 1, K);            // cb^T: [D][K]
    conv_gemm<1, false, false><<<dim3(BT / BM, K / BN, 1), 256>>>(
        bufB, wT, nullptr, scores, BT, D, K, K, -2.f);
    argmin_kernel<<<BT / 8, 256>>>(scores, cn, idxp);
    gather_kernel<<<(BT * 128 + 255) / 256, 256>>>(cb, idxp, bufA);  // q -> bufA

    // ---- decoder conv1: bufA -> bufB, relu ----
    transpose_w<<<256, 256>>>(dec_w1, wT, H, D, 3, H);
    conv_gemm<3, true, true><<<dim3(T / BM, H / BN, B), 256>>>(
        bufA, wT, dec_b1, bufB, T, D, H, H, 1.f);

    // ---- decoder conv2: bufB -> recon (directly into d_out, [B,T,80]) ----
    transpose_w<<<256, 256>>>(dec_w2, wT, IN, H, 3, 128);
    float* recon = (float*)d_out;
    conv_gemm<3, false, true><<<dim3(T / BM, 1, B), 256>>>(
        bufB, wT, dec_b2, recon, T, H, IN, 128, 1.f);

    // ---- idx tail (tuple output flattened as float32), if the harness expects it ----
    if (out_size >= RECON + BT) {
        idx_to_float<<<(BT + 255) / 256, 256>>>(idxp, recon + RECON, BT);
    }
}